// round 11
// baseline (speedup 1.0000x reference)
#include <cuda_runtime.h>

#define R_ 8
#define K_ 10
#define D_ 256
#define DL_ 10
#define B_ 4096
#define MT 64
#define NT_ 64          // number of row tiles = B_/MT
#define ZSTR 132        // 132 mod 32 = 4 -> conflict-friendly; k-slots of 12 floats

// ---------------- device scratch (static, no allocs) ----------------
__device__ float    g_P[R_ * K_ * 56];                 // packed symmetric Gram
__device__ unsigned g_xp[NT_ * 16 * 4 * 64 * 4];       // x tf32 frag-order [tile][kb][tig][row]{4k}  (4MB)
__device__ unsigned g_u1[R_ * 13 * 16 * 32 * 4];       // GEMM1 B frags [r][tile13][kb16][lane]{4k}   (1MB)
__device__ unsigned g_u2[R_ * 32 * 7 * 32 * 4];        // GEMM2 B frags [r][tileN32][kb7][lane]{4j}   (0.9MB)

__device__ __forceinline__ unsigned tf32b(float f) {
    unsigned u;
    asm("cvt.rna.tf32.f32 %0, %1;" : "=r"(u) : "f"(f));
    return u;
}
__device__ __forceinline__ void mma8(float* c, unsigned a0, unsigned a1,
                                     unsigned a2, unsigned a3,
                                     unsigned b0, unsigned b1) {
    asm volatile(
        "mma.sync.aligned.m16n8k8.row.col.f32.tf32.tf32.f32 "
        "{%0,%1,%2,%3}, {%4,%5,%6,%7}, {%8,%9}, {%0,%1,%2,%3};"
        : "+f"(c[0]), "+f"(c[1]), "+f"(c[2]), "+f"(c[3])
        : "r"(a0), "r"(a1), "r"(a2), "r"(a3), "r"(b0), "r"(b1));
}

// ---------------- fused prep kernel ----------------
// blocks [0,256):   xpack  tile = b>>2, quarter = b&3
// blocks [256,336): gram   rk   = b-256
// blocks [336,440): upack1 idx  = b-336  (r*13+tile)
// blocks [440,696): upack2 idx  = b-440  (r*32+tile)
__global__ void __launch_bounds__(256)
ks_prep(const float* __restrict__ x, const float* __restrict__ Us) {
    const int b = blockIdx.x, tidb = threadIdx.x;

    if (b < 256) {                      // ---- xpack (quarter tiles) ----
        const int tile = b >> 2, q = b & 3;
        #pragma unroll
        for (int it = 0; it < 4; it++) {
            const int e = q * 1024 + it * 256 + tidb;
            const int row = e & 63, kt = e >> 6;
            const int k0 = (kt >> 2) * 16 + (kt & 3) * 4;
            const float* xp = x + (size_t)(tile * 64 + row) * D_ + k0;
            uint4 v;
            v.x = tf32b(xp[0]); v.y = tf32b(xp[1]);
            v.z = tf32b(xp[2]); v.w = tf32b(xp[3]);
            ((uint4*)g_xp)[(size_t)tile * 4096 + e] = v;
        }
    } else if (b < 336) {               // ---- gram ----
        __shared__ float u[D_ * DL_];
        __shared__ float G[DL_ * DL_];
        const int rk = b - 256;
        const float* Up = Us + (size_t)rk * D_ * DL_;
        for (int i = tidb; i < D_ * DL_; i += 256) u[i] = Up[i];
        __syncthreads();
        if (tidb < DL_ * DL_) {
            const int i = tidb / DL_, j = tidb % DL_;
            float s = 0.0f;
            #pragma unroll 8
            for (int dd = 0; dd < D_; dd++) s += u[dd * DL_ + i] * u[dd * DL_ + j];
            G[tidb] = s;
        }
        __syncthreads();
        if (tidb < 55) {
            int tt = tidb, i = 0;
            while (tt >= DL_ - i) { tt -= DL_ - i; i++; }
            const int j = i + tt;
            g_P[rk * 56 + tidb] = G[i * DL_ + j] * (i == j ? 1.0f : 2.0f);
        }
    } else if (b < 440) {               // ---- upack1 ----
        const int idx = b - 336;
        const int r = idx / 13, tile = idx % 13;
        for (int e = tidb; e < 512; e += 256) {
            const int lane = e & 31, kb = e >> 5;
            const int g = lane >> 2, tig = lane & 3;
            const int j = tile * 8 + g, k0 = kb * 16 + tig * 4;
            uint4 v = make_uint4(0u, 0u, 0u, 0u);
            if (j < 100) {
                const float* up = Us + ((size_t)(r * 10 + j / 10) * D_ + k0) * 10 + (j % 10);
                v.x = tf32b(up[0]);  v.y = tf32b(up[10]);
                v.z = tf32b(up[20]); v.w = tf32b(up[30]);
            }
            ((uint4*)g_u1)[((r * 13 + tile) * 16 + kb) * 32 + lane] = v;
        }
    } else {                            // ---- upack2 ----
        const int idx = b - 440;
        const int r = idx >> 5, tile = idx & 31;
        if (tidb < 224) {
            const int lane = tidb & 31, kb = tidb >> 5;
            const int g = lane >> 2, tig = lane & 3;
            const int dd = tile * 8 + g, j0 = kb * 16 + tig * 4;
            unsigned w[4];
            #pragma unroll
            for (int q = 0; q < 4; q++) {
                const int j = j0 + q;
                w[q] = (j < 100)
                    ? tf32b(Us[((size_t)(r * 10 + j / 10) * D_ + dd) * 10 + (j % 10)])
                    : 0u;
            }
            ((uint4*)g_u2)[((r * 32 + tile) * 7 + kb) * 32 + lane] =
                make_uint4(w[0], w[1], w[2], w[3]);
        }
    }
}

// ---------------- smem layout (bytes) ----------------
#define SM_W    0          // 64 x 512B  w fragments (GEMM2 A operand)
#define SM_ZW   32768      // 64 x 132 x 4 = 33792
#define SM_GP   66560      // 2240
#define SMEM_TOTAL 68800   // x3 CTAs = 206 KB <= 227 KB

// ---------------- main fused kernel (3 CTAs/SM) ----------------
extern "C" __global__ void __launch_bounds__(256, 3)
ks_main(float* __restrict__ out) {
    extern __shared__ __align__(128) char smem[];
    const int tid = threadIdx.x, wid = tid >> 5, lane = tid & 31;
    const int g = lane >> 2, tig = lane & 3;
    const int r = blockIdx.y, tile = blockIdx.x, b0 = tile * MT;
    const int mw = wid >> 2, nw = wid & 3;
    const unsigned sxb = (unsigned)((g & 1) << 6);

    float* ZW  = (float*)(smem + SM_ZW);
    float* GP  = (float*)(smem + SM_GP);

    for (int i = tid; i < 560; i += 256) GP[i] = g_P[r * 560 + i];

    // ======== GEMM1: z[64][100] = x[64][256] @ Ucat  (mw2 x nw4, full K) ========
    {
        const uint4* XP = (const uint4*)g_xp + (size_t)tile * 4096
                        + (tig * 64 + mw * 32 + g);
        const uint4* U1b[4];
        int tv[4];
        #pragma unroll
        for (int nt = 0; nt < 4; nt++) {
            const int t13 = nw + 4 * nt;
            tv[nt] = t13 < 13;
            U1b[nt] = (const uint4*)g_u1 + ((size_t)(r * 13 + (tv[nt] ? t13 : 0)) * 16) * 32 + lane;
        }

        float acc[2][4][4];
        #pragma unroll
        for (int mt = 0; mt < 2; mt++)
            #pragma unroll
            for (int nt = 0; nt < 4; nt++)
                #pragma unroll
                for (int q = 0; q < 4; q++) acc[mt][nt][q] = 0.0f;

        #pragma unroll 2
        for (int kb = 0; kb < 16; kb++) {
            uint4 a[2][2];
            #pragma unroll
            for (int mt = 0; mt < 2; mt++)
                #pragma unroll
                for (int h = 0; h < 2; h++)
                    a[mt][h] = XP[kb * 256 + mt * 16 + 8 * h];
            uint4 b[4];
            #pragma unroll
            for (int nt = 0; nt < 4; nt++)
                if (tv[nt]) b[nt] = U1b[nt][kb * 32];
            #pragma unroll
            for (int nt = 0; nt < 4; nt++) {
                if (!tv[nt]) continue;
                #pragma unroll
                for (int mt = 0; mt < 2; mt++) {
                    mma8(acc[mt][nt], a[mt][0].x, a[mt][1].x, a[mt][0].y, a[mt][1].y,
                         b[nt].x, b[nt].y);
                    mma8(acc[mt][nt], a[mt][0].z, a[mt][1].z, a[mt][0].w, a[mt][1].w,
                         b[nt].z, b[nt].w);
                }
            }
        }
        #pragma unroll
        for (int mt = 0; mt < 2; mt++)
            #pragma unroll
            for (int nt = 0; nt < 4; nt++)
                if (tv[nt]) {
                    const int col = (nw + 4 * nt) * 8 + 2 * tig;   // even
                    const int ks = col / 10, d = col - ks * 10;
                    const int r0 = mw * 32 + mt * 16 + g;
                    *(float2*)(ZW + r0 * ZSTR + ks * 12 + d) =
                        make_float2(acc[mt][nt][0], acc[mt][nt][1]);
                    *(float2*)(ZW + (r0 + 8) * ZSTR + ks * 12 + d) =
                        make_float2(acc[mt][nt][2], acc[mt][nt][3]);
                }
    }
    __syncthreads();

    // ======== merged: logits + softmax (quad shuffles) + w-pack ========
    {
        const int row = tid >> 2, sub = tid & 3;
        const int nk = (sub < 2) ? 3 : 2;        // k = sub, sub+4, sub+8(sub<2)
        const float* zR = ZW + row * ZSTR;

        float z[3][10], lg[3], ex[3];
        float m = -1e30f;
        #pragma unroll
        for (int i = 0; i < 3; i++) {
            if (i >= nk) continue;
            const int k = sub + 4 * i;
            const float4 z0 = *(const float4*)(zR + k * 12);
            const float4 z1 = *(const float4*)(zR + k * 12 + 4);
            const float2 z2 = *(const float2*)(zR + k * 12 + 8);
            z[i][0] = z0.x; z[i][1] = z0.y; z[i][2] = z0.z; z[i][3] = z0.w;
            z[i][4] = z1.x; z[i][5] = z1.y; z[i][6] = z1.z; z[i][7] = z1.w;
            z[i][8] = z2.x; z[i][9] = z2.y;
            float s1 = 0.0f;
            #pragma unroll
            for (int d = 0; d < DL_; d++) s1 += z[i][d] * z[i][d];
            const float* Pk = GP + k * 56;
            float s2 = 0.0f; int tt = 0;
            #pragma unroll
            for (int i2 = 0; i2 < DL_; i2++)
                #pragma unroll
                for (int j2 = i2; j2 < DL_; j2++) { s2 += Pk[tt] * z[i][i2] * z[i][j2]; tt++; }
            lg[i] = 10.0f * s1 - 5.0f * s2;
            m = fmaxf(m, lg[i]);
        }
        m = fmaxf(m, __shfl_xor_sync(0xffffffffu, m, 1));
        m = fmaxf(m, __shfl_xor_sync(0xffffffffu, m, 2));
        float s = 0.0f;
        #pragma unroll
        for (int i = 0; i < 3; i++)
            if (i < nk) { ex[i] = __expf(lg[i] - m); s += ex[i]; }
        s += __shfl_xor_sync(0xffffffffu, s, 1);
        s += __shfl_xor_sync(0xffffffffu, s, 2);
        const float inv = 1.0f / s;

        const unsigned wb = SM_W + row * 512;
        const unsigned x6 = ((unsigned)(row & 1)) << 6;
        #pragma unroll
        for (int i = 0; i < 3; i++) {
            if (i >= nk) continue;
            const int k = sub + 4 * i;
            const float c = ex[i] * inv;
            #pragma unroll
            for (int d = 0; d < DL_; d++) {
                const int j = k * 10 + d;
                *(unsigned*)(smem + wb + (((unsigned)(j * 4)) ^ x6)) = tf32b(c * z[i][d]);
            }
        }
        #pragma unroll
        for (int i = 0; i < 3; i++) {           // zero-pad cols 100..111
            const int jp = 100 + sub * 3 + i;
            *(unsigned*)(smem + wb + (((unsigned)(jp * 4)) ^ x6)) = 0u;
        }
    }
    __syncthreads();

    // ======== GEMM2: out[64][256] = w[64][112] @ Ucat^T  (two N-passes) ========
    {
        const char* Ar[2][2];
        #pragma unroll
        for (int mt = 0; mt < 2; mt++)
            #pragma unroll
            for (int h = 0; h < 2; h++)
                Ar[mt][h] = smem + SM_W + (mw * 32 + mt * 16 + g + 8 * h) * 512;
        float* op = out + ((size_t)r * B_ + b0) * D_;

        #pragma unroll
        for (int pass = 0; pass < 2; pass++) {
            float acc2[2][4][4];
            #pragma unroll
            for (int mt = 0; mt < 2; mt++)
                #pragma unroll
                for (int nt = 0; nt < 4; nt++)
                    #pragma unroll
                    for (int q = 0; q < 4; q++) acc2[mt][nt][q] = 0.0f;

            const uint4* U2 = (const uint4*)g_u2 + (size_t)r * (32 * 7 * 32)
                            + (nw * 8 + pass * 4) * (7 * 32) + lane;

            #pragma unroll 2
            for (int kb = 0; kb < 7; kb++) {
                const unsigned ka = ((unsigned)(kb * 64 + tig * 16)) ^ sxb;
                uint4 a[2][2];
                #pragma unroll
                for (int mt = 0; mt < 2; mt++)
                    #pragma unroll
                    for (int h = 0; h < 2; h++)
                        a[mt][h] = *(const uint4*)(Ar[mt][h] + ka);
                #pragma unroll
                for (int nt = 0; nt < 4; nt++) {
                    const uint4 b = U2[(nt * 7 + kb) * 32];
                    #pragma unroll
                    for (int mt = 0; mt < 2; mt++) {
                        mma8(acc2[mt][nt], a[mt][0].x, a[mt][1].x, a[mt][0].y, a[mt][1].y,
                             b.x, b.y);
                        mma8(acc2[mt][nt], a[mt][0].z, a[mt][1].z, a[mt][0].w, a[mt][1].w,
                             b.z, b.w);
                    }
                }
            }
            // epilogue for this pass: direct STG.64 (32B chunks per quad)
            #pragma unroll
            for (int mt = 0; mt < 2; mt++) {
                const int r0 = mw * 32 + mt * 16 + g;
                #pragma unroll
                for (int nt = 0; nt < 4; nt++) {
                    const int col = (nw * 8 + pass * 4 + nt) * 8 + 2 * tig;
                    *(float2*)(op + r0 * D_ + col) =
                        make_float2(acc2[mt][nt][0], acc2[mt][nt][1]);
                    *(float2*)(op + (r0 + 8) * D_ + col) =
                        make_float2(acc2[mt][nt][2], acc2[mt][nt][3]);
                }
            }
        }
    }
}

extern "C" void kernel_launch(void* const* d_in, const int* in_sizes, int n_in,
                              void* d_out, int out_size) {
    const float* x  = (const float*)d_in[0];   // (4096, 256)
    const float* Us = (const float*)d_in[1];   // (8, 10, 256, 10)
    float* out = (float*)d_out;                // (8, 4096, 256)

    cudaFuncSetAttribute(ks_main, cudaFuncAttributeMaxDynamicSharedMemorySize,
                         SMEM_TOTAL);

    ks_prep<<<696, 256>>>(x, Us);

    dim3 grid(NT_, R_);
    ks_main<<<grid, 256, SMEM_TOTAL>>>(out);
}